// round 2
// baseline (speedup 1.0000x reference)
#include <cuda_runtime.h>

#define SEQ 512
#define D   256
#define NH  8
#define DH  32

// ---------------- scratch (device globals; no allocation) ----------------
__device__ float g_qp[SEQ * D];        // qp = q @ Wq^T          [512,256]
__device__ float g_a [SEQ * NH * D];   // effective queries      [512,8,256]
__device__ float g_w [SEQ * NH * D];   // attn-weighted v        [512,8,256]

// ============================================================
// Kernel A: qp[i,o] = sum_in q[i,in] * Wq[o,in]
// grid 128, 4 rows per block, 256 threads (thread = o)
// ============================================================
__global__ __launch_bounds__(256, 1)
void qp_kernel(const float* __restrict__ q, const float* __restrict__ Wq)
{
    __shared__ float q_s[4][D];
    int i0 = blockIdx.x * 4;
    for (int idx = threadIdx.x; idx < 4 * D; idx += 256)
        q_s[idx / D][idx % D] = q[(i0 + idx / D) * D + idx % D];
    __syncthreads();

    int o = threadIdx.x;
    const float* wrow = Wq + o * D;
    float acc[4] = {0.f, 0.f, 0.f, 0.f};
    for (int m = 0; m < D; m++) {
        float wv = wrow[m];
#pragma unroll
        for (int r = 0; r < 4; r++) acc[r] += q_s[r][m] * wv;
    }
#pragma unroll
    for (int r = 0; r < 4; r++) g_qp[(i0 + r) * D + o] = acc[r];
}

// ============================================================
// Kernel B: effective queries
//   a[i,n,k] = sum_{j' in 0..31} qp[i, n*32+j'] * Pk[i, n*32+j', k]
//   Pk[i,j,k] = sum_m qp[i,m] * Wk[(j*256+k)*256 + m]
// grid 128 = (n:8) x (itile:8, 64 rows) x (khalf:2, 128 cols)
// threads 256: tx = k-group (4 k), ty = i-group (8 i)
// ============================================================
__global__ __launch_bounds__(256, 1)
void effq_kernel(const float* __restrict__ Wk)
{
    extern __shared__ float sm[];
    float (*qp_s)[D]   = (float(*)[D])sm;              // 64 x 256
    float (*Bs)[132]   = (float(*)[132])(sm + 64 * D); // 32(m) x 128(k) +pad

    int b  = blockIdx.x;
    int n  = b >> 4;
    int it = (b >> 1) & 7;
    int kh = b & 1;
    int i0 = it * 64;
    int k0 = kh * 128;

    int tid = threadIdx.x;
    int tx  = tid & 31;   // k_local = tx*4
    int ty  = tid >> 5;   // ii = ty*8 + u

    // load qp tile (64 rows)
    for (int idx = tid; idx < 64 * (D / 4); idx += 256) {
        int r = idx >> 6, c = idx & 63;
        ((float4*)&qp_s[r][0])[c] = ((const float4*)&g_qp[(i0 + r) * D])[c];
    }
    __syncthreads();

    float a_acc[8][4];
#pragma unroll
    for (int u = 0; u < 8; u++)
#pragma unroll
        for (int v = 0; v < 4; v++) a_acc[u][v] = 0.f;

    for (int jj = 0; jj < 32; jj++) {
        int j = n * 32 + jj;
        const float* Wbase = Wk + (size_t)(j * 256 + k0) * D;

        float pk[8][4];
#pragma unroll
        for (int u = 0; u < 8; u++)
#pragma unroll
            for (int v = 0; v < 4; v++) pk[u][v] = 0.f;

        for (int mt = 0; mt < 8; mt++) {
            int m0 = mt * 32;
            // load W[(k0+kk), m0..m0+32) transposed -> Bs[mm][kk]
            {
                int kk = tid >> 1;
                int h  = tid & 1;
                const float4* src = (const float4*)(Wbase + (size_t)kk * D + m0 + h * 16);
#pragma unroll
                for (int c4 = 0; c4 < 4; c4++) {
                    float4 vv = src[c4];
                    int mm = h * 16 + c4 * 4;
                    Bs[mm + 0][kk] = vv.x; Bs[mm + 1][kk] = vv.y;
                    Bs[mm + 2][kk] = vv.z; Bs[mm + 3][kk] = vv.w;
                }
            }
            __syncthreads();
#pragma unroll
            for (int m4 = 0; m4 < 8; m4++) {
                float4 aq[8];
#pragma unroll
                for (int u = 0; u < 8; u++)
                    aq[u] = *(const float4*)&qp_s[ty * 8 + u][m0 + m4 * 4];
#pragma unroll
                for (int c = 0; c < 4; c++) {
                    float4 bv = *(const float4*)&Bs[m4 * 4 + c][tx * 4];
#pragma unroll
                    for (int u = 0; u < 8; u++) {
                        float av = (c == 0) ? aq[u].x : (c == 1) ? aq[u].y
                                 : (c == 2) ? aq[u].z : aq[u].w;
                        pk[u][0] += av * bv.x; pk[u][1] += av * bv.y;
                        pk[u][2] += av * bv.z; pk[u][3] += av * bv.w;
                    }
                }
            }
            __syncthreads();
        }
        // fold: a += qp[i, j] * Pk
#pragma unroll
        for (int u = 0; u < 8; u++) {
            float qj = qp_s[ty * 8 + u][j];
#pragma unroll
            for (int v = 0; v < 4; v++) a_acc[u][v] += qj * pk[u][v];
        }
    }
#pragma unroll
    for (int u = 0; u < 8; u++) {
        int i = i0 + ty * 8 + u;
        float4 vv = make_float4(a_acc[u][0], a_acc[u][1], a_acc[u][2], a_acc[u][3]);
        *(float4*)&g_a[((size_t)i * NH + n) * D + k0 + tx * 4] = vv;
    }
}

// ============================================================
// Kernel C: logits -> causal softmax -> w = probs @ v  (fused)
// grid 256 = (n:8) x (itile:32, 16 rows), threads 256
// ============================================================
__global__ __launch_bounds__(256, 1)
void attn_kernel(const float* __restrict__ kmat, const float* __restrict__ vmat)
{
    extern __shared__ float sm[];
    float (*a_s)[D]    = (float(*)[D])sm;                        // 16 x 256
    float (*l_s)[SEQ]  = (float(*)[SEQ])(sm + 16 * D);           // 16 x 512
    float (*kv_s)[257] = (float(*)[257])(sm + 16 * D + 16 * SEQ);// 32 x 257

    int n  = blockIdx.x >> 5;
    int i0 = (blockIdx.x & 31) * 16;
    int tid = threadIdx.x;
    const float scale = 0.04419417382415922f; // 1/sqrt(512)

    for (int idx = tid; idx < 16 * (D / 4); idx += 256) {
        int r = idx >> 6, c = idx & 63;
        ((float4*)&a_s[r][0])[c] =
            ((const float4*)&g_a[((size_t)(i0 + r) * NH + n) * D])[c];
    }

    int imax = i0 + 15;
    int nt   = (imax >> 5) + 1;   // valid 32-wide t tiles (causal)
    int T    = nt * 32;

    // ---- phase 1: logits ----
    for (int t4 = 0; t4 < nt; t4++) {
        int t0 = t4 * 32;
        __syncthreads();
        {
            int tt = tid >> 3;
            int mb = (tid & 7) * 4;
#pragma unroll
            for (int e = 0; e < 8; e++) {
                int m = mb + e * 32;
                float4 vv = *(const float4*)&kmat[(t0 + tt) * D + m];
                kv_s[tt][m + 0] = vv.x; kv_s[tt][m + 1] = vv.y;
                kv_s[tt][m + 2] = vv.z; kv_s[tt][m + 3] = vv.w;
            }
        }
        __syncthreads();
        int tt = tid & 31, r0 = tid >> 5;
        float acc0 = 0.f, acc1 = 0.f;
#pragma unroll 4
        for (int m = 0; m < D; m++) {
            float kvv = kv_s[tt][m];
            acc0 += a_s[r0][m] * kvv;
            acc1 += a_s[r0 + 8][m] * kvv;
        }
        l_s[r0][t0 + tt]     = acc0 * scale;
        l_s[r0 + 8][t0 + tt] = acc1 * scale;
    }
    __syncthreads();

    // ---- causal mask ----
    for (int r = 0; r < 16; r++) {
        int ir = i0 + r;
        for (int t = tid; t < T; t += 256)
            if (t > ir) l_s[r][t] = -1e30f;
    }
    __syncthreads();

    // ---- softmax: warp per row (2 rows per warp) ----
    int wid = tid >> 5, lane = tid & 31;
    for (int rr = 0; rr < 2; rr++) {
        int r = wid + rr * 8;
        float mx = -1e30f;
        for (int t = lane; t < T; t += 32) mx = fmaxf(mx, l_s[r][t]);
#pragma unroll
        for (int off = 16; off > 0; off >>= 1)
            mx = fmaxf(mx, __shfl_xor_sync(0xffffffffu, mx, off));
        float sum = 0.f;
        for (int t = lane; t < T; t += 32) {
            float e = __expf(l_s[r][t] - mx);
            l_s[r][t] = e;
            sum += e;
        }
#pragma unroll
        for (int off = 16; off > 0; off >>= 1)
            sum += __shfl_xor_sync(0xffffffffu, sum, off);
        float inv = 1.f / sum;
        for (int t = lane; t < T; t += 32) l_s[r][t] *= inv;
    }

    // ---- phase 2: w = probs @ v ----
    float w_acc[16];
#pragma unroll
    for (int r = 0; r < 16; r++) w_acc[r] = 0.f;

    for (int t4 = 0; t4 < nt; t4++) {
        int t0 = t4 * 32;
        __syncthreads();
        {
            int tt = tid >> 3;
            int mb = (tid & 7) * 4;
#pragma unroll
            for (int e = 0; e < 8; e++) {
                int m = mb + e * 32;
                float4 vv = *(const float4*)&vmat[(t0 + tt) * D + m];
                kv_s[tt][m + 0] = vv.x; kv_s[tt][m + 1] = vv.y;
                kv_s[tt][m + 2] = vv.z; kv_s[tt][m + 3] = vv.w;
            }
        }
        __syncthreads();
        int kk = tid;
#pragma unroll 4
        for (int tt = 0; tt < 32; tt++) {
            float vv = kv_s[tt][kk];
#pragma unroll
            for (int r = 0; r < 16; r++) w_acc[r] += l_s[r][t0 + tt] * vv;
        }
    }
#pragma unroll
    for (int r = 0; r < 16; r++)
        g_w[((size_t)(i0 + r) * NH + n) * D + tid] = w_acc[r];
}

// ============================================================
// Kernel D: out[i,j] = sum_k Pv[i,j,k] * w[i, n(j), k]
//   Pv[i,j,k] = sum_m qp[i,m] * Wv[(j*256+k)*256 + m]
// grid 128 = (n:8) x (itile:8, 64 rows) x (jhalf:2, 16 j)
// threads 256: tx = k-group (8 k), ty = i-group (8 i)
// ============================================================
__global__ __launch_bounds__(256, 1)
void outp_kernel(const float* __restrict__ Wv, float* __restrict__ out)
{
    extern __shared__ float sm[];
    float (*qp_s)[D]  = (float(*)[D])sm;                 // 64 x 256
    float (*w_s)[D]   = (float(*)[D])(sm + 64 * D);      // 64 x 256
    float (*Bs)[260]  = (float(*)[260])(sm + 128 * D);   // 32(m) x 256(k) +pad

    int b  = blockIdx.x;
    int n  = b >> 4;
    int it = (b >> 1) & 7;
    int jh = b & 1;
    int i0 = it * 64;

    int tid = threadIdx.x;
    int tx  = tid & 31;  // k = tx*8 + v
    int ty  = tid >> 5;  // ii = ty*8 + u

    for (int idx = tid; idx < 64 * (D / 4); idx += 256) {
        int r = idx >> 6, c = idx & 63;
        ((float4*)&qp_s[r][0])[c] = ((const float4*)&g_qp[(i0 + r) * D])[c];
        ((float4*)&w_s[r][0])[c] =
            ((const float4*)&g_w[((size_t)(i0 + r) * NH + n) * D])[c];
    }
    __syncthreads();

    for (int jj = 0; jj < 16; jj++) {
        int j = n * 32 + jh * 16 + jj;
        const float* Wbase = Wv + (size_t)j * 256 * D;

        float pv[8][8];
#pragma unroll
        for (int u = 0; u < 8; u++)
#pragma unroll
            for (int v = 0; v < 8; v++) pv[u][v] = 0.f;

        for (int mt = 0; mt < 8; mt++) {
            int m0 = mt * 32;
            // load Wv rows (j*256 + kk), m0..m0+32 transposed -> Bs[mm][kk]
#pragma unroll
            for (int p = 0; p < 8; p++) {
                int kk = p * 32 + (tid >> 3);
                float4 vv = *(const float4*)(Wbase + (size_t)kk * D + m0 + (tid & 7) * 4);
                int mm = (tid & 7) * 4;
                Bs[mm + 0][kk] = vv.x; Bs[mm + 1][kk] = vv.y;
                Bs[mm + 2][kk] = vv.z; Bs[mm + 3][kk] = vv.w;
            }
            __syncthreads();
#pragma unroll
            for (int m4 = 0; m4 < 8; m4++) {
                float4 aq[8];
#pragma unroll
                for (int u = 0; u < 8; u++)
                    aq[u] = *(const float4*)&qp_s[ty * 8 + u][m0 + m4 * 4];
#pragma unroll
                for (int c = 0; c < 4; c++) {
                    float4 b0 = *(const float4*)&Bs[m4 * 4 + c][tx * 8];
                    float4 b1 = *(const float4*)&Bs[m4 * 4 + c][tx * 8 + 4];
#pragma unroll
                    for (int u = 0; u < 8; u++) {
                        float av = (c == 0) ? aq[u].x : (c == 1) ? aq[u].y
                                 : (c == 2) ? aq[u].z : aq[u].w;
                        pv[u][0] += av * b0.x; pv[u][1] += av * b0.y;
                        pv[u][2] += av * b0.z; pv[u][3] += av * b0.w;
                        pv[u][4] += av * b1.x; pv[u][5] += av * b1.y;
                        pv[u][6] += av * b1.z; pv[u][7] += av * b1.w;
                    }
                }
            }
            __syncthreads();
        }

        // dot Pv against w over the thread's 8 k, then warp-reduce over tx
        float part[8];
#pragma unroll
        for (int u = 0; u < 8; u++) {
            float4 w0 = *(const float4*)&w_s[ty * 8 + u][tx * 8];
            float4 w1 = *(const float4*)&w_s[ty * 8 + u][tx * 8 + 4];
            part[u] = w0.x * pv[u][0] + w0.y * pv[u][1] + w0.z * pv[u][2] + w0.w * pv[u][3]
                    + w1.x * pv[u][4] + w1.y * pv[u][5] + w1.z * pv[u][6] + w1.w * pv[u][7];
        }
#pragma unroll
        for (int off = 16; off > 0; off >>= 1)
#pragma unroll
            for (int u = 0; u < 8; u++)
                part[u] += __shfl_xor_sync(0xffffffffu, part[u], off);

        if (tx == 0) {
#pragma unroll
            for (int u = 0; u < 8; u++)
                out[(i0 + ty * 8 + u) * D + j] = part[u];
        }
    }
}

// ============================================================
extern "C" void kernel_launch(void* const* d_in, const int* in_sizes, int n_in,
                              void* d_out, int out_size)
{
    const float* q   = (const float*)d_in[0];
    const float* kk  = (const float*)d_in[1];
    const float* vv  = (const float*)d_in[2];
    const float* Wq  = (const float*)d_in[3];
    const float* Wk  = (const float*)d_in[4];
    const float* Wv  = (const float*)d_in[5];
    // d_in[6] = mask (causal tril) — applied analytically in attn_kernel
    float* out = (float*)d_out;

    const int smemB = (64 * D + 32 * 132) * 4;               // 82432
    const int smemC = (16 * D + 16 * SEQ + 32 * 257) * 4;    // 82048
    const int smemD = (128 * D + 32 * 260) * 4;              // 164352

    // idempotent; ignore errors if called under capture (set on first real call)
    cudaFuncSetAttribute(effq_kernel, cudaFuncAttributeMaxDynamicSharedMemorySize, smemB);
    cudaFuncSetAttribute(attn_kernel, cudaFuncAttributeMaxDynamicSharedMemorySize, smemC);
    cudaFuncSetAttribute(outp_kernel, cudaFuncAttributeMaxDynamicSharedMemorySize, smemD);

    qp_kernel<<<SEQ / 4, 256>>>(q, Wq);
    effq_kernel<<<128, 256, smemB>>>(Wk);
    attn_kernel<<<256, 256, smemC>>>(kk, vv);
    outp_kernel<<<128, 256, smemD>>>(Wv, out);
}

// round 4
// speedup vs baseline: 2.3116x; 2.3116x over previous
#include <cuda_runtime.h>
#include <cuda_bf16.h>
#include <cstdint>

#define SEQ 512
#define D   256
#define NH  8

// ---------------- scratch (device globals; no allocation) ----------------
__device__ float g_qp[SEQ * D];                      // qp fp32
__device__ __nv_bfloat16 g_qp_hi[SEQ * D];
__device__ __nv_bfloat16 g_qp_lo[SEQ * D];
__device__ __nv_bfloat16 g_Wk_hi[65536 * 256];
__device__ __nv_bfloat16 g_Wk_lo[65536 * 256];
__device__ __nv_bfloat16 g_Wv_hi[65536 * 256];
__device__ __nv_bfloat16 g_Wv_lo[65536 * 256];
__device__ float g_P[256 * 512 * 256];               // cube [j][i][k] fp32, 134MB
__device__ float g_a [SEQ * NH * D];                 // effective queries
__device__ float g_w [SEQ * NH * D];                 // attn-weighted v

// ---------------- helpers ----------------
__device__ __forceinline__ uint32_t smem_u32(const void* p) {
    uint32_t a;
    asm("{ .reg .u64 t; cvta.to.shared.u64 t, %1; cvt.u32.u64 %0, t; }" : "=r"(a) : "l"(p));
    return a;
}
__device__ __forceinline__ void cpa16(uint32_t s, const void* g) {
    asm volatile("cp.async.cg.shared.global [%0], [%1], 16;" :: "r"(s), "l"(g) : "memory");
}
__device__ __forceinline__ void ldsm_x4(uint32_t r[4], uint32_t addr) {
    asm volatile("ldmatrix.sync.aligned.m8n8.x4.shared.b16 {%0,%1,%2,%3}, [%4];"
        : "=r"(r[0]), "=r"(r[1]), "=r"(r[2]), "=r"(r[3]) : "r"(addr));
}
__device__ __forceinline__ void ldsm_x2(uint32_t r[2], uint32_t addr) {
    asm volatile("ldmatrix.sync.aligned.m8n8.x2.shared.b16 {%0,%1}, [%2];"
        : "=r"(r[0]), "=r"(r[1]) : "r"(addr));
}
__device__ __forceinline__ void mma16816(float c[4], const uint32_t a[4], const uint32_t b[2]) {
    asm volatile("mma.sync.aligned.m16n8k16.row.col.f32.bf16.bf16.f32 "
        "{%0,%1,%2,%3}, {%4,%5,%6,%7}, {%8,%9}, {%0,%1,%2,%3};"
        : "+f"(c[0]), "+f"(c[1]), "+f"(c[2]), "+f"(c[3])
        : "r"(a[0]), "r"(a[1]), "r"(a[2]), "r"(a[3]), "r"(b[0]), "r"(b[1]));
}

// ============================================================
// prep: fp32 -> bf16 hi/lo splits for Wk, Wv
// ============================================================
__global__ __launch_bounds__(256, 1)
void prep_kernel(const float* __restrict__ Wk, const float* __restrict__ Wv)
{
    const long total4 = 2L * 16777216L / 4L;
    for (long idx = (long)blockIdx.x * blockDim.x + threadIdx.x; idx < total4;
         idx += (long)gridDim.x * blockDim.x) {
        bool isK = idx < 4194304L;
        long l = isK ? idx : idx - 4194304L;
        float4 v = isK ? ((const float4*)Wk)[l] : ((const float4*)Wv)[l];
        __nv_bfloat16* hi = (isK ? g_Wk_hi : g_Wv_hi) + l * 4;
        __nv_bfloat16* lo = (isK ? g_Wk_lo : g_Wv_lo) + l * 4;
        __nv_bfloat16 h0 = __float2bfloat16(v.x), h1 = __float2bfloat16(v.y);
        __nv_bfloat16 h2 = __float2bfloat16(v.z), h3 = __float2bfloat16(v.w);
        ((__nv_bfloat162*)hi)[0] = __nv_bfloat162(h0, h1);
        ((__nv_bfloat162*)hi)[1] = __nv_bfloat162(h2, h3);
        ((__nv_bfloat162*)lo)[0] = __nv_bfloat162(
            __float2bfloat16(v.x - __bfloat162float(h0)),
            __float2bfloat16(v.y - __bfloat162float(h1)));
        ((__nv_bfloat162*)lo)[1] = __nv_bfloat162(
            __float2bfloat16(v.z - __bfloat162float(h2)),
            __float2bfloat16(v.w - __bfloat162float(h3)));
    }
}

// ============================================================
// Kernel A: qp = q @ Wq^T  (+ bf16 hi/lo split)
// ============================================================
__global__ __launch_bounds__(256, 1)
void qp_kernel(const float* __restrict__ q, const float* __restrict__ Wq)
{
    __shared__ float q_s[4][D];
    int i0 = blockIdx.x * 4;
    for (int idx = threadIdx.x; idx < 4 * D; idx += 256)
        q_s[idx / D][idx % D] = q[(i0 + idx / D) * D + idx % D];
    __syncthreads();

    int o = threadIdx.x;
    const float* wrow = Wq + o * D;
    float acc[4] = {0.f, 0.f, 0.f, 0.f};
    for (int m = 0; m < D; m++) {
        float wv = wrow[m];
#pragma unroll
        for (int r = 0; r < 4; r++) acc[r] += q_s[r][m] * wv;
    }
#pragma unroll
    for (int r = 0; r < 4; r++) {
        float x = acc[r];
        int off = (i0 + r) * D + o;
        g_qp[off] = x;
        __nv_bfloat16 h = __float2bfloat16(x);
        g_qp_hi[off] = h;
        g_qp_lo[off] = __float2bfloat16(x - __bfloat162float(h));
    }
}

// ============================================================
// cube_gemm: P[j][i][k] = sum_m qp[i,m] * W[(j*256+k), m]   (bf16x3, HMMA)
//   grid 2048: j = bx>>3, i0 = ((bx>>1)&3)*128, kh = bx&1
//   CTA tile 128(i) x 128(k), K=256 in 4 chunks of 64, cp.async 2-stage
//   8 warps: wr = wid>>2 (i 64), wc = wid&3 (k 32); warp tile 64x32
// ============================================================
#define SA 144          // smem bytes per row (64 bf16 + 16B pad: conflict-free ldmatrix)
#define ARR 18432       // 128 rows * 144
#define STAGE 73728     // 4 arrays (Ah, Al, Bh, Bl)

__global__ __launch_bounds__(256, 1)
void cube_gemm(const __nv_bfloat16* __restrict__ Wh,
               const __nv_bfloat16* __restrict__ Wl,
               float* __restrict__ Pout)
{
    extern __shared__ char smem[];
    uint32_t sbase = smem_u32(smem);
    int tid = threadIdx.x, lane = tid & 31, wid = tid >> 5;
    int wr = wid >> 2, wc = wid & 3;

    int j  = blockIdx.x >> 3;
    int i0 = ((blockIdx.x >> 1) & 3) * 128;
    int kh = blockIdx.x & 1;
    long jb = (long)j * 256 + kh * 128;

    const __nv_bfloat16* Ah = g_qp_hi;
    const __nv_bfloat16* Al = g_qp_lo;

    auto load = [&](int c, int s) {
        uint32_t st = sbase + s * STAGE;
        int m0 = c * 64;
#pragma unroll
        for (int p = 0; p < 4; p++) {
            int idx = p * 256 + tid;
            int r = idx >> 3, ss = idx & 7;
            uint32_t so = (uint32_t)(r * SA + ss * 16);
            cpa16(st + so,            Ah + (i0 + r) * 256 + m0 + ss * 8);
            cpa16(st + ARR + so,      Al + (i0 + r) * 256 + m0 + ss * 8);
            cpa16(st + 2 * ARR + so,  Wh + (jb + r) * 256 + m0 + ss * 8);
            cpa16(st + 3 * ARR + so,  Wl + (jb + r) * 256 + m0 + ss * 8);
        }
        asm volatile("cp.async.commit_group;" ::: "memory");
    };

    float acc[4][4][4];
#pragma unroll
    for (int mt = 0; mt < 4; mt++)
#pragma unroll
        for (int nt = 0; nt < 4; nt++)
#pragma unroll
            for (int e = 0; e < 4; e++) acc[mt][nt][e] = 0.f;

    load(0, 0);
    load(1, 1);

    for (int c = 0; c < 4; c++) {
        if (c < 3) asm volatile("cp.async.wait_group 1;" ::: "memory");
        else       asm volatile("cp.async.wait_group 0;" ::: "memory");
        __syncthreads();
        uint32_t st  = sbase + (c & 1) * STAGE;
        uint32_t aB  = st, alB = st + ARR, bB = st + 2 * ARR, blB = st + 3 * ARR;
#pragma unroll
        for (int ks = 0; ks < 4; ks++) {
            uint32_t bh[4][2], bl[4][2];
#pragma unroll
            for (int nt = 0; nt < 4; nt++) {
                uint32_t off = (uint32_t)((wc * 32 + nt * 8 + (lane & 7)) * SA
                             + ((lane >> 3) & 1) * 16 + ks * 32);
                ldsm_x2(bh[nt], bB + off);
                ldsm_x2(bl[nt], blB + off);
            }
#pragma unroll
            for (int mt = 0; mt < 4; mt++) {
                uint32_t off = (uint32_t)((wr * 64 + mt * 16 + (lane & 15)) * SA
                             + (lane >> 4) * 16 + ks * 32);
                uint32_t ah[4], al[4];
                ldsm_x4(ah, aB + off);
                ldsm_x4(al, alB + off);
#pragma unroll
                for (int nt = 0; nt < 4; nt++) {
                    mma16816(acc[mt][nt], ah, bh[nt]);
                    mma16816(acc[mt][nt], ah, bl[nt]);
                    mma16816(acc[mt][nt], al, bh[nt]);
                }
            }
        }
        __syncthreads();
        if (c + 2 < 4) load(c + 2, c & 1);
    }

    // epilogue: write fp32 cube
    int g = lane >> 2, qq = lane & 3;
#pragma unroll
    for (int mt = 0; mt < 4; mt++) {
        int ir = i0 + wr * 64 + mt * 16 + g;
        float* base0 = Pout + ((size_t)j * 512 + ir) * 256;
        float* base1 = base0 + 8 * 256;
#pragma unroll
        for (int nt = 0; nt < 4; nt++) {
            int kk = kh * 128 + wc * 32 + nt * 8 + qq * 2;
            *(float2*)(base0 + kk) = make_float2(acc[mt][nt][0], acc[mt][nt][1]);
            *(float2*)(base1 + kk) = make_float2(acc[mt][nt][2], acc[mt][nt][3]);
        }
    }
}

// ============================================================
// kfold: a[i,n,k] = sum_jj qp[i, n*32+jj] * P[n*32+jj][i][k]
// grid 4096 = i*8+n, 128 threads (2 k per thread)
// ============================================================
__global__ __launch_bounds__(128, 1)
void kfold_kernel()
{
    __shared__ float qs[32];
    int i = blockIdx.x >> 3;
    int n = blockIdx.x & 7;
    int tid = threadIdx.x;
    if (tid < 32) qs[tid] = g_qp[i * 256 + n * 32 + tid];
    __syncthreads();

    const float2* base = (const float2*)g_P
                       + ((size_t)(n * 32) * 512 + i) * 128 + tid;
    float ax = 0.f, ay = 0.f;
#pragma unroll 8
    for (int jj = 0; jj < 32; jj++) {
        float2 p = base[(size_t)jj * 65536];
        float s = qs[jj];
        ax += s * p.x; ay += s * p.y;
    }
    ((float2*)g_a)[((size_t)i * NH + n) * 128 + tid] = make_float2(ax, ay);
}

// ============================================================
// vfold: out[i,j] = sum_k P[j][i][k] * w[i, j>>5, k]
// grid 4096 = i*8+n, 256 threads; warp handles 4 j
// ============================================================
__global__ __launch_bounds__(256, 1)
void vfold_kernel(float* __restrict__ out)
{
    __shared__ float w_s[256];
    int i = blockIdx.x >> 3;
    int n = blockIdx.x & 7;
    int tid = threadIdx.x, lane = tid & 31, wid = tid >> 5;
    w_s[tid] = g_w[((size_t)i * NH + n) * 256 + tid];
    __syncthreads();

    float4 w0 = *(const float4*)(w_s + lane * 8);
    float4 w1 = *(const float4*)(w_s + lane * 8 + 4);
#pragma unroll
    for (int q = 0; q < 4; q++) {
        int j = n * 32 + wid * 4 + q;
        const float4* p = (const float4*)(g_P + ((size_t)j * 512 + i) * 256) + lane * 2;
        float4 p0 = p[0], p1 = p[1];
        float s = w0.x * p0.x + w0.y * p0.y + w0.z * p0.z + w0.w * p0.w
                + w1.x * p1.x + w1.y * p1.y + w1.z * p1.z + w1.w * p1.w;
#pragma unroll
        for (int off = 16; off > 0; off >>= 1)
            s += __shfl_xor_sync(0xffffffffu, s, off);
        if (lane == 0) out[(size_t)i * 256 + j] = s;
    }
}

// ============================================================
// attn: logits -> causal softmax -> w = probs @ v  (fused)
// ============================================================
__global__ __launch_bounds__(256, 1)
void attn_kernel(const float* __restrict__ kmat, const float* __restrict__ vmat)
{
    extern __shared__ float sm[];
    float (*a_s)[D]    = (float(*)[D])sm;                        // 16 x 256
    float (*l_s)[SEQ]  = (float(*)[SEQ])(sm + 16 * D);           // 16 x 512
    float (*kv_s)[257] = (float(*)[257])(sm + 16 * D + 16 * SEQ);// 32 x 257

    int n  = blockIdx.x >> 5;
    int i0 = (blockIdx.x & 31) * 16;
    int tid = threadIdx.x;
    const float scale = 0.04419417382415922f; // 1/sqrt(512)

    for (int idx = tid; idx < 16 * (D / 4); idx += 256) {
        int r = idx >> 6, c = idx & 63;
        ((float4*)&a_s[r][0])[c] =
            ((const float4*)&g_a[((size_t)(i0 + r) * NH + n) * D])[c];
    }

    int imax = i0 + 15;
    int nt   = (imax >> 5) + 1;
    int T    = nt * 32;

    for (int t4 = 0; t4 < nt; t4++) {
        int t0 = t4 * 32;
        __syncthreads();
        {
            int tt = tid >> 3;
            int mb = (tid & 7) * 4;
#pragma unroll
            for (int e = 0; e < 8; e++) {
                int m = mb + e * 32;
                float4 vv = *(const float4*)&kmat[(t0 + tt) * D + m];
                kv_s[tt][m + 0] = vv.x; kv_s[tt][m + 1] = vv.y;
                kv_s[tt][m + 2] = vv.z; kv_s[tt][m + 3] = vv.w;
            }
        }
        __syncthreads();
        int tt = tid & 31, r0 = tid >> 5;
        float acc0 = 0.f, acc1 = 0.f;
#pragma unroll 4
        for (int m = 0; m < D; m++) {
            float kvv = kv_s[tt][m];
            acc0 += a_s[r0][m] * kvv;
            acc1 += a_s[r0 + 8][m] * kvv;
        }
        l_s[r0][t0 + tt]     = acc0 * scale;
        l_s[r0 + 8][t0 + tt] = acc1 * scale;
    }
    __syncthreads();

    for (int r = 0; r < 16; r++) {
        int ir = i0 + r;
        for (int t = tid; t < T; t += 256)
            if (t > ir) l_s[r][t] = -1e30f;
    }
    __syncthreads();

    int wid = tid >> 5, lane = tid & 31;
    for (int rr = 0; rr < 2; rr++) {
        int r = wid + rr * 8;
        float mx = -1e30f;
        for (int t = lane; t < T; t += 32) mx = fmaxf(mx, l_s[r][t]);
#pragma unroll
        for (int off = 16; off > 0; off >>= 1)
            mx = fmaxf(mx, __shfl_xor_sync(0xffffffffu, mx, off));
        float sum = 0.f;
        for (int t = lane; t < T; t += 32) {
            float e = __expf(l_s[r][t] - mx);
            l_s[r][t] = e;
            sum += e;
        }
#pragma unroll
        for (int off = 16; off > 0; off >>= 1)
            sum += __shfl_xor_sync(0xffffffffu, sum, off);
        float inv = 1.f / sum;
        for (int t = lane; t < T; t += 32) l_s[r][t] *= inv;
    }

    float w_acc[16];
#pragma unroll
    for (int r = 0; r < 16; r++) w_acc[r] = 0.f;

    for (int t4 = 0; t4 < nt; t4++) {
        int t0 = t4 * 32;
        __syncthreads();
        {
            int tt = tid >> 3;
            int mb = (tid & 7) * 4;
#pragma unroll
            for (int e = 0; e < 8; e++) {
                int m = mb + e * 32;
                float4 vv = *(const float4*)&vmat[(t0 + tt) * D + m];
                kv_s[tt][m + 0] = vv.x; kv_s[tt][m + 1] = vv.y;
                kv_s[tt][m + 2] = vv.z; kv_s[tt][m + 3] = vv.w;
            }
        }
        __syncthreads();
        int kk = tid;
#pragma unroll 4
        for (int tt = 0; tt < 32; tt++) {
            float vv = kv_s[tt][kk];
#pragma unroll
            for (int r = 0; r < 16; r++) w_acc[r] += l_s[r][t0 + tt] * vv;
        }
    }
#pragma unroll
    for (int r = 0; r < 16; r++)
        g_w[((size_t)(i0 + r) * NH + n) * D + tid] = w_acc[r];
}

// ============================================================
extern "C" void kernel_launch(void* const* d_in, const int* in_sizes, int n_in,
                              void* d_out, int out_size)
{
    const float* q   = (const float*)d_in[0];
    const float* kk  = (const float*)d_in[1];
    const float* vv  = (const float*)d_in[2];
    const float* Wq  = (const float*)d_in[3];
    const float* Wk  = (const float*)d_in[4];
    const float* Wv  = (const float*)d_in[5];
    float* out = (float*)d_out;

    const int smemG = 2 * STAGE;                              // 147456
    const int smemC = (16 * D + 16 * SEQ + 32 * 257) * 4;     // 82048

    cudaFuncSetAttribute(cube_gemm,   cudaFuncAttributeMaxDynamicSharedMemorySize, smemG);
    cudaFuncSetAttribute(attn_kernel, cudaFuncAttributeMaxDynamicSharedMemorySize, smemC);

    __nv_bfloat16 *wk_hi, *wk_lo, *wv_hi, *wv_lo;
    float* gP;
    cudaGetSymbolAddress((void**)&wk_hi, g_Wk_hi);
    cudaGetSymbolAddress((void**)&wk_lo, g_Wk_lo);
    cudaGetSymbolAddress((void**)&wv_hi, g_Wv_hi);
    cudaGetSymbolAddress((void**)&wv_lo, g_Wv_lo);
    cudaGetSymbolAddress((void**)&gP,    g_P);

    prep_kernel<<<8192, 256>>>(Wk, Wv);
    qp_kernel<<<SEQ / 4, 256>>>(q, Wq);
    cube_gemm<<<2048, 256, smemG>>>(wk_hi, wk_lo, gP);   // Pk cube
    kfold_kernel<<<4096, 128>>>();                       // -> g_a
    attn_kernel<<<256, 256, smemC>>>(kk, vv);            // -> g_w
    cube_gemm<<<2048, 256, smemG>>>(wv_hi, wv_lo, gP);   // Pv cube (reuses buffer)
    vfold_kernel<<<4096, 256>>>(out);                    // -> out
}

// round 6
// speedup vs baseline: 2.8528x; 1.2341x over previous
#include <cuda_runtime.h>
#include <cuda_bf16.h>
#include <cstdint>

#define SEQ 512
#define D   256
#define NH  8

// ---------------- scratch (device globals; no allocation) ----------------
__device__ float g_qp[SEQ * D];
__device__ __nv_bfloat16 g_qp_hi[SEQ * D];
__device__ __nv_bfloat16 g_qp_lo[SEQ * D];
__device__ __nv_bfloat16 g_Wk_hi[65536 * 256];
__device__ __nv_bfloat16 g_Wk_lo[65536 * 256];
__device__ __nv_bfloat16 g_Wv_hi[65536 * 256];
__device__ __nv_bfloat16 g_Wv_lo[65536 * 256];
__device__ float g_P[256 * 512 * 256];               // Pk cube [j][i][k] fp32
__device__ __nv_bfloat16 g_a_hi[SEQ * NH * D];       // scaled effective queries
__device__ __nv_bfloat16 g_a_lo[SEQ * NH * D];
__device__ __nv_bfloat16 g_k_hi[SEQ * D];
__device__ __nv_bfloat16 g_k_lo[SEQ * D];
__device__ __nv_bfloat16 g_v_hi[SEQ * D];
__device__ __nv_bfloat16 g_v_lo[SEQ * D];
__device__ float g_w[SEQ * NH * D];                  // attn-weighted v
__device__ float g_part[2 * SEQ * D];                // out partials per k-half

// ---------------- helpers ----------------
__device__ __forceinline__ uint32_t smem_u32(const void* p) {
    uint32_t a;
    asm("{ .reg .u64 t; cvta.to.shared.u64 t, %1; cvt.u32.u64 %0, t; }" : "=r"(a) : "l"(p));
    return a;
}
__device__ __forceinline__ void cpa16(uint32_t s, const void* g) {
    asm volatile("cp.async.cg.shared.global [%0], [%1], 16;" :: "r"(s), "l"(g) : "memory");
}
#define CP_COMMIT() asm volatile("cp.async.commit_group;" ::: "memory")
#define CP_WAIT(n)  asm volatile("cp.async.wait_group %0;" :: "n"(n) : "memory")
__device__ __forceinline__ void ldsm_x4(uint32_t r[4], uint32_t addr) {
    asm volatile("ldmatrix.sync.aligned.m8n8.x4.shared.b16 {%0,%1,%2,%3}, [%4];"
        : "=r"(r[0]), "=r"(r[1]), "=r"(r[2]), "=r"(r[3]) : "r"(addr));
}
__device__ __forceinline__ void ldsm_x4t(uint32_t r[4], uint32_t addr) {
    asm volatile("ldmatrix.sync.aligned.m8n8.x4.trans.shared.b16 {%0,%1,%2,%3}, [%4];"
        : "=r"(r[0]), "=r"(r[1]), "=r"(r[2]), "=r"(r[3]) : "r"(addr));
}
__device__ __forceinline__ void ldsm_x2(uint32_t r[2], uint32_t addr) {
    asm volatile("ldmatrix.sync.aligned.m8n8.x2.shared.b16 {%0,%1}, [%2];"
        : "=r"(r[0]), "=r"(r[1]) : "r"(addr));
}
__device__ __forceinline__ void mma16816(float c[4], const uint32_t a[4], const uint32_t b[2]) {
    asm volatile("mma.sync.aligned.m16n8k16.row.col.f32.bf16.bf16.f32 "
        "{%0,%1,%2,%3}, {%4,%5,%6,%7}, {%8,%9}, {%0,%1,%2,%3};"
        : "+f"(c[0]), "+f"(c[1]), "+f"(c[2]), "+f"(c[3])
        : "r"(a[0]), "r"(a[1]), "r"(a[2]), "r"(a[3]), "r"(b[0]), "r"(b[1]));
}
__device__ __forceinline__ void mma16816_2(float c[4], const uint32_t a[4],
                                           uint32_t b0, uint32_t b1) {
    asm volatile("mma.sync.aligned.m16n8k16.row.col.f32.bf16.bf16.f32 "
        "{%0,%1,%2,%3}, {%4,%5,%6,%7}, {%8,%9}, {%0,%1,%2,%3};"
        : "+f"(c[0]), "+f"(c[1]), "+f"(c[2]), "+f"(c[3])
        : "r"(a[0]), "r"(a[1]), "r"(a[2]), "r"(a[3]), "r"(b0), "r"(b1));
}

// ============================================================
// prep: fp32 -> bf16 hi/lo splits for Wk, Wv
// ============================================================
__global__ __launch_bounds__(256, 1)
void prep_kernel(const float* __restrict__ Wk, const float* __restrict__ Wv)
{
    const long total4 = 2L * 16777216L / 4L;
    for (long idx = (long)blockIdx.x * blockDim.x + threadIdx.x; idx < total4;
         idx += (long)gridDim.x * blockDim.x) {
        bool isK = idx < 4194304L;
        long l = isK ? idx : idx - 4194304L;
        float4 v = isK ? ((const float4*)Wk)[l] : ((const float4*)Wv)[l];
        __nv_bfloat16* hi = (isK ? g_Wk_hi : g_Wv_hi) + l * 4;
        __nv_bfloat16* lo = (isK ? g_Wk_lo : g_Wv_lo) + l * 4;
        __nv_bfloat16 h0 = __float2bfloat16(v.x), h1 = __float2bfloat16(v.y);
        __nv_bfloat16 h2 = __float2bfloat16(v.z), h3 = __float2bfloat16(v.w);
        ((__nv_bfloat162*)hi)[0] = __nv_bfloat162(h0, h1);
        ((__nv_bfloat162*)hi)[1] = __nv_bfloat162(h2, h3);
        ((__nv_bfloat162*)lo)[0] = __nv_bfloat162(
            __float2bfloat16(v.x - __bfloat162float(h0)),
            __float2bfloat16(v.y - __bfloat162float(h1)));
        ((__nv_bfloat162*)lo)[1] = __nv_bfloat162(
            __float2bfloat16(v.z - __bfloat162float(h2)),
            __float2bfloat16(v.w - __bfloat162float(h3)));
    }
}

// prep2: split k, v
__global__ __launch_bounds__(256, 1)
void prep2_kernel(const float* __restrict__ kin, const float* __restrict__ vin)
{
    int idx = blockIdx.x * 256 + threadIdx.x;
    for (int e = 0; e < 2; e++) {
        int l = idx * 2 + e;
        float kv = kin[l], vv = vin[l];
        __nv_bfloat16 kh = __float2bfloat16(kv), vh = __float2bfloat16(vv);
        g_k_hi[l] = kh; g_k_lo[l] = __float2bfloat16(kv - __bfloat162float(kh));
        g_v_hi[l] = vh; g_v_lo[l] = __float2bfloat16(vv - __bfloat162float(vh));
    }
}

// ============================================================
// Kernel A: qp = q @ Wq^T  (+ bf16 hi/lo split)
// ============================================================
__global__ __launch_bounds__(256, 1)
void qp_kernel(const float* __restrict__ q, const float* __restrict__ Wq)
{
    __shared__ float q_s[4][D];
    int i0 = blockIdx.x * 4;
    for (int idx = threadIdx.x; idx < 4 * D; idx += 256)
        q_s[idx / D][idx % D] = q[(i0 + idx / D) * D + idx % D];
    __syncthreads();

    int o = threadIdx.x;
    const float* wrow = Wq + o * D;
    float acc[4] = {0.f, 0.f, 0.f, 0.f};
    for (int m = 0; m < D; m++) {
        float wv = wrow[m];
#pragma unroll
        for (int r = 0; r < 4; r++) acc[r] += q_s[r][m] * wv;
    }
#pragma unroll
    for (int r = 0; r < 4; r++) {
        float x = acc[r];
        int off = (i0 + r) * D + o;
        g_qp[off] = x;
        __nv_bfloat16 h = __float2bfloat16(x);
        g_qp_hi[off] = h;
        g_qp_lo[off] = __float2bfloat16(x - __bfloat162float(h));
    }
}

// ============================================================
// cube_gemm: D[i,k] = sum_m qp[i,m] * W[(j*256+k), m]   (bf16x3, HMMA)
//   mode 0: write fp32 cube g_P[j][i][k]
//   mode 1: fused V-fold: g_part[kh][i][j] = sum_{k in half} D[i,k]*w[i,n,k]
// ============================================================
#define SA 144
#define ARR 18432
#define STAGE 73728

__global__ __launch_bounds__(256, 1)
void cube_gemm(const __nv_bfloat16* __restrict__ Wh,
               const __nv_bfloat16* __restrict__ Wl,
               int mode, float* __restrict__ Pout)
{
    extern __shared__ char smem[];
    uint32_t sbase = smem_u32(smem);
    int tid = threadIdx.x, lane = tid & 31, wid = tid >> 5;
    int wr = wid >> 2, wc = wid & 3;

    int j  = blockIdx.x >> 3;
    int i0 = ((blockIdx.x >> 1) & 3) * 128;
    int kh = blockIdx.x & 1;
    long jb = (long)j * 256 + kh * 128;

    const __nv_bfloat16* Ah = g_qp_hi;
    const __nv_bfloat16* Al = g_qp_lo;

    auto load = [&](int c, int s) {
        uint32_t st = sbase + s * STAGE;
        int m0 = c * 64;
#pragma unroll
        for (int p = 0; p < 4; p++) {
            int idx = p * 256 + tid;
            int r = idx >> 3, ss = idx & 7;
            uint32_t so = (uint32_t)(r * SA + ss * 16);
            cpa16(st + so,            Ah + (i0 + r) * 256 + m0 + ss * 8);
            cpa16(st + ARR + so,      Al + (i0 + r) * 256 + m0 + ss * 8);
            cpa16(st + 2 * ARR + so,  Wh + (jb + r) * 256 + m0 + ss * 8);
            cpa16(st + 3 * ARR + so,  Wl + (jb + r) * 256 + m0 + ss * 8);
        }
        CP_COMMIT();
    };

    float acc[4][4][4];
#pragma unroll
    for (int mt = 0; mt < 4; mt++)
#pragma unroll
        for (int nt = 0; nt < 4; nt++)
#pragma unroll
            for (int e = 0; e < 4; e++) acc[mt][nt][e] = 0.f;

    load(0, 0);
    load(1, 1);

    for (int c = 0; c < 4; c++) {
        if (c < 3) CP_WAIT(1); else CP_WAIT(0);
        __syncthreads();
        uint32_t st  = sbase + (c & 1) * STAGE;
        uint32_t aB  = st, alB = st + ARR, bB = st + 2 * ARR, blB = st + 3 * ARR;
#pragma unroll
        for (int ks = 0; ks < 4; ks++) {
            uint32_t bh[4][2], bl[4][2];
#pragma unroll
            for (int nt = 0; nt < 4; nt++) {
                uint32_t off = (uint32_t)((wc * 32 + nt * 8 + (lane & 7)) * SA
                             + ((lane >> 3) & 1) * 16 + ks * 32);
                ldsm_x2(bh[nt], bB + off);
                ldsm_x2(bl[nt], blB + off);
            }
#pragma unroll
            for (int mt = 0; mt < 4; mt++) {
                uint32_t off = (uint32_t)((wr * 64 + mt * 16 + (lane & 15)) * SA
                             + (lane >> 4) * 16 + ks * 32);
                uint32_t ah[4], al[4];
                ldsm_x4(ah, aB + off);
                ldsm_x4(al, alB + off);
#pragma unroll
                for (int nt = 0; nt < 4; nt++) {
                    mma16816(acc[mt][nt], ah, bh[nt]);
                    mma16816(acc[mt][nt], ah, bl[nt]);
                    mma16816(acc[mt][nt], al, bh[nt]);
                }
            }
        }
        __syncthreads();
        if (c + 2 < 4) load(c + 2, c & 1);
    }

    int g = lane >> 2, qq = lane & 3;
    if (mode == 0) {
#pragma unroll
        for (int mt = 0; mt < 4; mt++) {
            int ir = i0 + wr * 64 + mt * 16 + g;
            float* base0 = Pout + ((size_t)j * 512 + ir) * 256;
            float* base1 = base0 + 8 * 256;
#pragma unroll
            for (int nt = 0; nt < 4; nt++) {
                int kk = kh * 128 + wc * 32 + nt * 8 + qq * 2;
                *(float2*)(base0 + kk) = make_float2(acc[mt][nt][0], acc[mt][nt][1]);
                *(float2*)(base1 + kk) = make_float2(acc[mt][nt][2], acc[mt][nt][3]);
            }
        }
    } else {
        // fused V-fold epilogue
        int n = j >> 5;
        float (*sred)[4] = (float(*)[4])smem;   // [128][4]
#pragma unroll
        for (int mt = 0; mt < 4; mt++) {
            int ir0 = i0 + wr * 64 + mt * 16 + g;
            int ir1 = ir0 + 8;
            float p0 = 0.f, p1 = 0.f;
#pragma unroll
            for (int nt = 0; nt < 4; nt++) {
                int kk = kh * 128 + wc * 32 + nt * 8 + qq * 2;
                float2 w0 = *(const float2*)&g_w[((size_t)ir0 * NH + n) * 256 + kk];
                float2 w1 = *(const float2*)&g_w[((size_t)ir1 * NH + n) * 256 + kk];
                p0 += acc[mt][nt][0] * w0.x + acc[mt][nt][1] * w0.y;
                p1 += acc[mt][nt][2] * w1.x + acc[mt][nt][3] * w1.y;
            }
#pragma unroll
            for (int off = 1; off <= 2; off <<= 1) {
                p0 += __shfl_xor_sync(0xffffffffu, p0, off);
                p1 += __shfl_xor_sync(0xffffffffu, p1, off);
            }
            if (qq == 0) {
                sred[wr * 64 + mt * 16 + g][wc]     = p0;
                sred[wr * 64 + mt * 16 + g + 8][wc] = p1;
            }
        }
        __syncthreads();
        if (tid < 128) {
            float s = sred[tid][0] + sred[tid][1] + sred[tid][2] + sred[tid][3];
            g_part[((size_t)kh * 512 + i0 + tid) * 256 + j] = s;
        }
    }
}

// combine: out = part0 + part1
__global__ __launch_bounds__(256, 1)
void combine_kernel(float* __restrict__ out)
{
    int i = blockIdx.x, j = threadIdx.x;
    out[i * 256 + j] = g_part[(size_t)i * 256 + j] + g_part[(size_t)(512 + i) * 256 + j];
}

// ============================================================
// kfold: a[i,n,k] = scale * sum_jj qp[i, n*32+jj] * P[n*32+jj][i][k]
// ============================================================
__global__ __launch_bounds__(128, 1)
void kfold_kernel()
{
    __shared__ float qs[32];
    int i = blockIdx.x >> 3;
    int n = blockIdx.x & 7;
    int tid = threadIdx.x;
    if (tid < 32) qs[tid] = g_qp[i * 256 + n * 32 + tid];
    __syncthreads();

    const float2* base = (const float2*)g_P
                       + ((size_t)(n * 32) * 512 + i) * 128 + tid;
    float ax = 0.f, ay = 0.f;
#pragma unroll 8
    for (int jj = 0; jj < 32; jj++) {
        float2 p = base[(size_t)jj * 65536];
        float s = qs[jj];
        ax += s * p.x; ay += s * p.y;
    }
    const float rs = 0.04419417382415922f;   // 1/sqrt(512)
    ax *= rs; ay *= rs;
    __nv_bfloat16 hx = __float2bfloat16(ax);
    __nv_bfloat16 hy = __float2bfloat16(ay);
    __nv_bfloat16 lx = __float2bfloat16(ax - __bfloat162float(hx));
    __nv_bfloat16 ly = __float2bfloat16(ay - __bfloat162float(hy));
    size_t o = ((size_t)i * NH + n) * 128 + tid;
    ((__nv_bfloat162*)g_a_hi)[o] = __nv_bfloat162(hx, hy);
    ((__nv_bfloat162*)g_a_lo)[o] = __nv_bfloat162(lx, ly);
}

// ============================================================
// flash_attn: w[i,n,:] = softmax_causal(a.k^T).v  (bf16x3 MMA, online softmax)
// ============================================================
#define FA_A_HI  0
#define FA_A_LO  16896      // 32*528
#define FA_KBUF  33792
#define FA_KSTG  36864
#define FA_VLO   33792
#define FA_P     107520
#define FA_PLO   8704       // 32*272
#define FA_STATS 124928
#define SMEM_FA  126464

__global__ __launch_bounds__(256, 1)
void flash_attn()
{
    extern __shared__ char smem[];
    uint32_t sb = smem_u32(smem);
    int tid = threadIdx.x, lane = tid & 31, wid = tid >> 5;
    int wi = wid & 1, wh = wid >> 1;
    int n = blockIdx.x >> 4;
    int b = blockIdx.x & 15;
    int i0 = b * 32;

    float* sMaxP = (float*)(smem + FA_STATS);   // [4][32]
    float* sSumP = sMaxP + 128;                 // [4][32]
    float* sM    = sSumP + 128;                 // [32]
    float* sL    = sM + 32;
    float* sF    = sL + 32;

    // load A (a_hi/lo): 32 rows x 32 chunks = 1024 transfers -> p < 4   (BUGFIX)
#pragma unroll
    for (int p = 0; p < 4; p++) {
        int idx = p * 256 + tid;
        int r = idx >> 5, c = idx & 31;
        cpa16(sb + FA_A_HI + r * 528 + c * 16, g_a_hi + ((size_t)(i0 + r) * NH + n) * 256 + c * 8);
        cpa16(sb + FA_A_LO + r * 528 + c * 16, g_a_lo + ((size_t)(i0 + r) * NH + n) * 256 + c * 8);
    }
    CP_COMMIT();
    if (tid < 32) { sM[tid] = -1e30f; sL[tid] = 0.f; }

    float O[8][4];
#pragma unroll
    for (int t = 0; t < 8; t++)
#pragma unroll
        for (int e = 0; e < 4; e++) O[t][e] = 0.f;

    auto kload = [&](int t0, int mc, int s) {
        uint32_t st = sb + FA_KBUF + s * FA_KSTG;
#pragma unroll
        for (int p = 0; p < 4; p++) {
            int idx = p * 256 + tid;
            int r = idx >> 3, c = idx & 7;
            cpa16(st + r * 144 + c * 16,         g_k_hi + (t0 + r) * 256 + mc * 64 + c * 8);
            cpa16(st + 18432 + r * 144 + c * 16, g_k_lo + (t0 + r) * 256 + mc * 64 + c * 8);
        }
        CP_COMMIT();
    };
    auto vload = [&](int t0, int tc) {
        uint32_t st = sb + FA_KBUF;
#pragma unroll
        for (int p = 0; p < 8; p++) {
            int idx = p * 256 + tid;
            int r = idx >> 5, c = idx & 31;
            cpa16(st + r * 528 + c * 16,          g_v_hi + (t0 + tc * 64 + r) * 256 + c * 8);
            cpa16(st + FA_VLO + r * 528 + c * 16, g_v_lo + (t0 + tc * 64 + r) * 256 + c * 8);
        }
        CP_COMMIT();
    };

    int g = lane >> 2, qq = lane & 3;
    int ntiles = (b + 4) >> 2;
    for (int tt = 0; tt < ntiles; tt++) {
        int t0 = tt * 128;
        kload(t0, 0, 0);
        kload(t0, 1, 1);

        float s[4][4];
#pragma unroll
        for (int nt = 0; nt < 4; nt++)
#pragma unroll
            for (int e = 0; e < 4; e++) s[nt][e] = 0.f;

        for (int mc = 0; mc < 4; mc++) {
            if (mc < 3) CP_WAIT(1); else CP_WAIT(0);
            __syncthreads();
            uint32_t kb = sb + FA_KBUF + (mc & 1) * FA_KSTG;
            uint32_t aH = sb + FA_A_HI + (wi * 16 + (lane & 15)) * 528
                        + (lane >> 4) * 16 + mc * 128;
#pragma unroll
            for (int ks = 0; ks < 4; ks++) {
                uint32_t ah[4], al[4];
                ldsm_x4(ah, aH + ks * 32);
                ldsm_x4(al, aH + (FA_A_LO - FA_A_HI) + ks * 32);
#pragma unroll
                for (int nt = 0; nt < 4; nt++) {
                    uint32_t bo = kb + (wh * 32 + nt * 8 + (lane & 7)) * 144
                                + ((lane >> 3) & 1) * 16 + ks * 32;
                    uint32_t bh[2], bl[2];
                    ldsm_x2(bh, bo);
                    ldsm_x2(bl, bo + 18432);
                    mma16816(s[nt], ah, bh);
                    mma16816(s[nt], ah, bl);
                    mma16816(s[nt], al, bh);
                }
            }
            __syncthreads();
            if (mc < 2) kload(t0, mc + 2, mc & 1);
        }

        if (tt == ntiles - 1) {
#pragma unroll
            for (int nt = 0; nt < 4; nt++) {
                int tbase = t0 + wh * 32 + nt * 8 + qq * 2;
                int ig0 = i0 + wi * 16 + g, ig1 = ig0 + 8;
                if (tbase     > ig0) s[nt][0] = -1e30f;
                if (tbase + 1 > ig0) s[nt][1] = -1e30f;
                if (tbase     > ig1) s[nt][2] = -1e30f;
                if (tbase + 1 > ig1) s[nt][3] = -1e30f;
            }
        }

        float mx0 = -1e30f, mx1 = -1e30f;
#pragma unroll
        for (int nt = 0; nt < 4; nt++) {
            mx0 = fmaxf(mx0, fmaxf(s[nt][0], s[nt][1]));
            mx1 = fmaxf(mx1, fmaxf(s[nt][2], s[nt][3]));
        }
#pragma unroll
        for (int off = 1; off <= 2; off <<= 1) {
            mx0 = fmaxf(mx0, __shfl_xor_sync(0xffffffffu, mx0, off));
            mx1 = fmaxf(mx1, __shfl_xor_sync(0xffffffffu, mx1, off));
        }
        if (qq == 0) {
            sMaxP[wh * 32 + wi * 16 + g]     = mx0;
            sMaxP[wh * 32 + wi * 16 + g + 8] = mx1;
        }
        __syncthreads();

        int r0 = wi * 16 + g, r1 = r0 + 8;
        float mn0 = fmaxf(fmaxf(sM[r0], fmaxf(sMaxP[r0], sMaxP[32 + r0])),
                          fmaxf(sMaxP[64 + r0], sMaxP[96 + r0]));
        float mn1 = fmaxf(fmaxf(sM[r1], fmaxf(sMaxP[r1], sMaxP[32 + r1])),
                          fmaxf(sMaxP[64 + r1], sMaxP[96 + r1]));

        float sum0 = 0.f, sum1 = 0.f;
#pragma unroll
        for (int nt = 0; nt < 4; nt++) {
            float p0 = __expf(s[nt][0] - mn0);
            float p1 = __expf(s[nt][1] - mn0);
            float p2 = __expf(s[nt][2] - mn1);
            float p3 = __expf(s[nt][3] - mn1);
            sum0 += p0 + p1; sum1 += p2 + p3;
            __nv_bfloat16 h0 = __float2bfloat16(p0), h1 = __float2bfloat16(p1);
            __nv_bfloat16 h2 = __float2bfloat16(p2), h3 = __float2bfloat16(p3);
            __nv_bfloat162 lo01(__float2bfloat16(p0 - __bfloat162float(h0)),
                                __float2bfloat16(p1 - __bfloat162float(h1)));
            __nv_bfloat162 lo23(__float2bfloat16(p2 - __bfloat162float(h2)),
                                __float2bfloat16(p3 - __bfloat162float(h3)));
            uint32_t colb = (wh * 32 + nt * 8 + qq * 2) * 2;
            *(__nv_bfloat162*)(smem + FA_P + r0 * 272 + colb) = __nv_bfloat162(h0, h1);
            *(__nv_bfloat162*)(smem + FA_P + r1 * 272 + colb) = __nv_bfloat162(h2, h3);
            *(__nv_bfloat162*)(smem + FA_P + FA_PLO + r0 * 272 + colb) = lo01;
            *(__nv_bfloat162*)(smem + FA_P + FA_PLO + r1 * 272 + colb) = lo23;
        }
#pragma unroll
        for (int off = 1; off <= 2; off <<= 1) {
            sum0 += __shfl_xor_sync(0xffffffffu, sum0, off);
            sum1 += __shfl_xor_sync(0xffffffffu, sum1, off);
        }
        if (qq == 0) {
            sSumP[wh * 32 + r0] = sum0;
            sSumP[wh * 32 + r1] = sum1;
        }
        __syncthreads();

        if (tid < 32) {
            float mold = sM[tid];
            float mn = fmaxf(fmaxf(mold, fmaxf(sMaxP[tid], sMaxP[32 + tid])),
                             fmaxf(sMaxP[64 + tid], sMaxP[96 + tid]));
            float f = __expf(mold - mn);
            sF[tid] = f;
            sL[tid] = sL[tid] * f + sSumP[tid] + sSumP[32 + tid]
                    + sSumP[64 + tid] + sSumP[96 + tid];
            sM[tid] = mn;
        }
        vload(t0, 0);
        __syncthreads();

        float f0 = sF[r0], f1 = sF[r1];
#pragma unroll
        for (int knt = 0; knt < 8; knt++) {
            O[knt][0] *= f0; O[knt][1] *= f0;
            O[knt][2] *= f1; O[knt][3] *= f1;
        }

        for (int tc = 0; tc < 2; tc++) {
            CP_WAIT(0);
            __syncthreads();
#pragma unroll
            for (int ks = 0; ks < 4; ks++) {
                uint32_t pa = sb + FA_P + (wi * 16 + (lane & 15)) * 272
                            + (lane >> 4) * 16 + tc * 128 + ks * 32;
                uint32_t ph[4], pl[4];
                ldsm_x4(ph, pa);
                ldsm_x4(pl, pa + FA_PLO);
#pragma unroll
                for (int ntp = 0; ntp < 4; ntp++) {
                    uint32_t vo = sb + FA_KBUF + (ks * 16 + (lane & 15)) * 528
                                + (wh * 64 + ntp * 16 + (lane >> 4) * 8) * 2;
                    uint32_t vh[4], vl[4];
                    ldsm_x4t(vh, vo);
                    ldsm_x4t(vl, vo + FA_VLO);
                    mma16816_2(O[ntp * 2],     ph, vh[0], vh[1]);
                    mma16816_2(O[ntp * 2],     ph, vl[0], vl[1]);
                    mma16816_2(O[ntp * 2],     pl, vh[0], vh[1]);
                    mma16816_2(O[ntp * 2 + 1], ph, vh[2], vh[3]);
                    mma16816_2(O[ntp * 2 + 1], ph, vl[2], vl[3]);
                    mma16816_2(O[ntp * 2 + 1], pl, vh[2], vh[3]);
                }
            }
            __syncthreads();
            if (tc == 0) vload(t0, 1);
        }
    }

    float il0 = 1.f / sL[wi * 16 + g];
    float il1 = 1.f / sL[wi * 16 + g + 8];
    int ig0 = i0 + wi * 16 + g, ig1 = ig0 + 8;
#pragma unroll
    for (int knt = 0; knt < 8; knt++) {
        int k = wh * 64 + knt * 8 + qq * 2;
        *(float2*)&g_w[((size_t)ig0 * NH + n) * 256 + k] =
            make_float2(O[knt][0] * il0, O[knt][1] * il0);
        *(float2*)&g_w[((size_t)ig1 * NH + n) * 256 + k] =
            make_float2(O[knt][2] * il1, O[knt][3] * il1);
    }
}

// ============================================================
extern "C" void kernel_launch(void* const* d_in, const int* in_sizes, int n_in,
                              void* d_out, int out_size)
{
    const float* q   = (const float*)d_in[0];
    const float* kk  = (const float*)d_in[1];
    const float* vv  = (const float*)d_in[2];
    const float* Wq  = (const float*)d_in[3];
    const float* Wk  = (const float*)d_in[4];
    const float* Wv  = (const float*)d_in[5];
    float* out = (float*)d_out;

    const int smemG = 2 * STAGE;   // 147456

    cudaFuncSetAttribute(cube_gemm,  cudaFuncAttributeMaxDynamicSharedMemorySize, smemG);
    cudaFuncSetAttribute(flash_attn, cudaFuncAttributeMaxDynamicSharedMemorySize, SMEM_FA);

    __nv_bfloat16 *wk_hi, *wk_lo, *wv_hi, *wv_lo;
    float* gP;
    cudaGetSymbolAddress((void**)&wk_hi, g_Wk_hi);
    cudaGetSymbolAddress((void**)&wk_lo, g_Wk_lo);
    cudaGetSymbolAddress((void**)&wv_hi, g_Wv_hi);
    cudaGetSymbolAddress((void**)&wv_lo, g_Wv_lo);
    cudaGetSymbolAddress((void**)&gP,    g_P);

    prep_kernel<<<8192, 256>>>(Wk, Wv);
    prep2_kernel<<<256, 256>>>(kk, vv);
    qp_kernel<<<SEQ / 4, 256>>>(q, Wq);
    cube_gemm<<<2048, 256, smemG>>>(wk_hi, wk_lo, 0, gP);   // Pk cube
    kfold_kernel<<<4096, 128>>>();                          // -> a hi/lo (scaled)
    flash_attn<<<128, 256, SMEM_FA>>>();                    // -> g_w
    cube_gemm<<<2048, 256, smemG>>>(wv_hi, wv_lo, 1, gP);   // fused V-fold -> g_part
    combine_kernel<<<512, 256>>>(out);                      // -> out
}